// round 10
// baseline (speedup 1.0000x reference)
#include <cuda_runtime.h>
#include <cuda_fp16.h>
#include <cstdint>
#include <math.h>

#define BB   32768
#define DRGB 512
#define DSPD 128
#define DIN  640
#define HH   256
#define CC   7

#define BM   128
#define BN   128
#define BK   64
#define NTHR 256
#define STAGE_BYTES 32768        // (128 + 128) rows * 128B  (standalone GEMM)
#define SMEM_BYTES  (2 * STAGE_BYTES)

// mega-kernel smem layout (byte offsets in dynamic smem)
#define MG_AST0 0
#define MG_AST1 16384
#define MG_BST0 32768
#define MG_BST1 49152
#define MG_H2   65536
#define MG_SMEM 131072           // 128KB

// ---------------- device scratch ----------------
__device__ int g_count[8];
__device__ int g_off[8];
__device__ int g_pos[8];
__device__ int g_perm[BB];
__device__ int g_off_full[2] = {0, BB};

__device__ __half g_s1[BB * DSPD];
__device__ __half g_s2[BB * DSPD];
__device__ __half g_xbf[(size_t)BB * DIN];     // sorted concat [rgb | sfeat]
__device__ __half g_h1[(size_t)BB * HH];

// fp16 transposed weights: [C][N][K]
__device__ __half g_W1t[(size_t)CC * HH * DIN];
__device__ __half g_W2t[(size_t)CC * HH * HH];
__device__ __half g_W3t[(size_t)CC * HH * HH];
__device__ __half g_sW2t[DSPD * DSPD];
__device__ __half g_sW3t[DSPD * DSPD];

__device__ __forceinline__ float sigmoidf_(float x) { return 1.0f / (1.0f + expf(-x)); }

// ---------------- PTX helpers ----------------
__device__ __forceinline__ uint32_t smem_u32(const void* p) {
    return (uint32_t)__cvta_generic_to_shared(p);
}
__device__ __forceinline__ void cp_async16(uint32_t dst, const void* src) {
    asm volatile("cp.async.cg.shared.global [%0], [%1], 16;\n" :: "r"(dst), "l"(src) : "memory");
}
__device__ __forceinline__ void cp_commit() { asm volatile("cp.async.commit_group;\n" ::: "memory"); }
template <int N> __device__ __forceinline__ void cp_wait() {
    asm volatile("cp.async.wait_group %0;\n" :: "n"(N) : "memory");
}
__device__ __forceinline__ void ldmx4(uint32_t& r0, uint32_t& r1, uint32_t& r2, uint32_t& r3,
                                      uint32_t addr) {
    asm volatile("ldmatrix.sync.aligned.m8n8.x4.shared.b16 {%0,%1,%2,%3}, [%4];"
                 : "=r"(r0), "=r"(r1), "=r"(r2), "=r"(r3) : "r"(addr));
}
__device__ __forceinline__ void mma16816(float* d, const uint32_t* a, const uint32_t* b) {
    asm volatile(
        "mma.sync.aligned.m16n8k16.row.col.f32.f16.f16.f32 "
        "{%0,%1,%2,%3}, {%4,%5,%6,%7}, {%8,%9}, {%0,%1,%2,%3};"
        : "+f"(d[0]), "+f"(d[1]), "+f"(d[2]), "+f"(d[3])
        : "r"(a[0]), "r"(a[1]), "r"(a[2]), "r"(a[3]), "r"(b[0]), "r"(b[1]));
}
__device__ __forceinline__ uint32_t packh2(float a, float b) {
    __half2 h = __floats2half2_rn(a, b);
    return *(uint32_t*)&h;
}

// one 64-col K-chunk of a 64x32 warp tile; A/B tiles are 128B-row XOR-swizzled
__device__ __forceinline__ void compute_chunk(uint32_t aB, uint32_t bB,
                                              float acc[4][4][4],
                                              int wm, int wn, int lane) {
#pragma unroll
    for (int ks = 0; ks < 4; ks++) {
        uint32_t a[4][4], b[4][2];
        int cbA = ks * 32 + ((lane >> 4) << 4);
#pragma unroll
        for (int mi = 0; mi < 4; mi++) {
            int r = wm + 16 * mi + (lane & 15);
            ldmx4(a[mi][0], a[mi][1], a[mi][2], a[mi][3],
                  aB + r * 128 + (uint32_t)(cbA ^ ((r & 7) << 4)));
        }
        int cbB = ks * 32 + ((lane & 8) << 1);
#pragma unroll
        for (int nj = 0; nj < 2; nj++) {
            int r = wn + 16 * nj + (lane & 7) + ((lane & 16) >> 1);
            uint32_t t0, t1, t2, t3;
            ldmx4(t0, t1, t2, t3, bB + r * 128 + (uint32_t)(cbB ^ ((r & 7) << 4)));
            b[2 * nj][0] = t0; b[2 * nj][1] = t1;
            b[2 * nj + 1][0] = t2; b[2 * nj + 1][1] = t3;
        }
#pragma unroll
        for (int mi = 0; mi < 4; mi++)
#pragma unroll
            for (int ni = 0; ni < 4; ni++)
                mma16816(acc[mi][ni], a[mi], b[ni]);
    }
}

// ---------------- bucketing ----------------
__global__ void zero_kernel() { if (threadIdx.x < 8) g_count[threadIdx.x] = 0; }

__global__ void hist_kernel(const int* __restrict__ cmd) {
    __shared__ int sc[8];
    if (threadIdx.x < 8) sc[threadIdx.x] = 0;
    __syncthreads();
    int i = blockIdx.x * blockDim.x + threadIdx.x;
    if (i < BB) atomicAdd(&sc[cmd[i]], 1);
    __syncthreads();
    if (threadIdx.x < 8 && sc[threadIdx.x]) atomicAdd(&g_count[threadIdx.x], sc[threadIdx.x]);
}

__global__ void scan_kernel() {
    g_off[0] = 0;
    for (int c = 0; c < CC; c++) g_off[c + 1] = g_off[c] + g_count[c];
    for (int c = 0; c < CC; c++) g_pos[c] = g_off[c];
}

__global__ void scatter_kernel(const int* __restrict__ cmd) {
    int i = blockIdx.x * blockDim.x + threadIdx.x;
    if (i >= BB) return;
    int c = cmd[i];
    int lane = threadIdx.x & 31;
    unsigned mask = __match_any_sync(0xFFFFFFFFu, c);
    int leader = __ffs(mask) - 1;
    int rank = __popc(mask & ((1u << lane) - 1));
    int base = 0;
    if (lane == leader) base = atomicAdd(&g_pos[c], __popc(mask));
    base = __shfl_sync(0xFFFFFFFFu, base, leader);
    g_perm[base + rank] = i;
}

// ---------------- weight transpose + fp32->fp16 (two tensors batched via z) ----------------
__global__ void transpose_h2_kernel(const float* __restrict__ srcA, __half* __restrict__ dstA,
                                    const float* __restrict__ srcB, __half* __restrict__ dstB,
                                    int R, int C_, int zsplit) {
    __shared__ float t[32][33];
    int z = blockIdx.z;
    const float* src = (z < zsplit) ? srcA : srcB;
    __half* dst = (z < zsplit) ? dstA : dstB;
    int zz = (z < zsplit) ? z : z - zsplit;
    src += (size_t)zz * R * C_;
    dst += (size_t)zz * R * C_;
    int c0 = blockIdx.x * 32, r0 = blockIdx.y * 32;
    int tx = threadIdx.x, ty = threadIdx.y;
#pragma unroll
    for (int k = 0; k < 4; k++)
        t[ty + 8 * k][tx] = src[(size_t)(r0 + ty + 8 * k) * C_ + c0 + tx];
    __syncthreads();
#pragma unroll
    for (int k = 0; k < 4; k++)
        dst[(size_t)(c0 + ty + 8 * k) * R + r0 + tx] = __float2half_rn(t[tx][ty + 8 * k]);
}

// ---------------- speed-MLP layer 1 (rank-1), sorted output, fp16 ----------------
__global__ void spd_l1_kernel(const float* __restrict__ spd,
                              const float* __restrict__ W1,
                              const float* __restrict__ b1) {
    int idx = blockIdx.x * blockDim.x + threadIdx.x;
    if (idx >= BB * 16) return;
    int p = idx >> 4;
    int j8 = (idx & 15) * 8;
    float s = spd[g_perm[p]];
    uint4 o;
    float4 w0 = *(const float4*)(W1 + j8), w1 = *(const float4*)(W1 + j8 + 4);
    float4 c0 = *(const float4*)(b1 + j8), c1 = *(const float4*)(b1 + j8 + 4);
    o.x = packh2(tanhf(fmaf(s, w0.x, c0.x)), tanhf(fmaf(s, w0.y, c0.y)));
    o.y = packh2(tanhf(fmaf(s, w0.z, c0.z)), tanhf(fmaf(s, w0.w, c0.w)));
    o.z = packh2(tanhf(fmaf(s, w1.x, c1.x)), tanhf(fmaf(s, w1.y, c1.y)));
    o.w = packh2(tanhf(fmaf(s, w1.z, c1.z)), tanhf(fmaf(s, w1.w, c1.w)));
    *(uint4*)(g_s1 + (size_t)p * DSPD + j8) = o;
}

// ---------------- rgb gather + fp32->fp16 ----------------
__global__ void gather_rgb_kernel(const float* __restrict__ rgb) {
    int idx = blockIdx.x * blockDim.x + threadIdx.x;
    if (idx >= BB * 64) return;
    int p = idx >> 6;
    int j8 = (idx & 63) * 8;
    int row = g_perm[p];
    float4 v0 = *(const float4*)(rgb + (size_t)row * DRGB + j8);
    float4 v1 = *(const float4*)(rgb + (size_t)row * DRGB + j8 + 4);
    uint4 o;
    o.x = packh2(v0.x, v0.y);
    o.y = packh2(v0.z, v0.w);
    o.z = packh2(v1.x, v1.y);
    o.w = packh2(v1.z, v1.w);
    *(uint4*)(g_xbf + (size_t)p * DIN + j8) = o;
}

// ---------------- standalone fp16 mma GEMM (speed layers + branch L1) ----------------
template <int K, int NTOT, int ACT, bool GROUPED>
__global__ void __launch_bounds__(NTHR)
mma_gemm_kernel(const __half* __restrict__ A,
                const __half* __restrict__ Wt,
                const float* __restrict__ Bbias,
                __half* __restrict__ Out, int out_stride, int coloff) {
    constexpr int NIT = K / BK;
    const int c = GROUPED ? blockIdx.z : 0;
    const int* off = GROUPED ? g_off : g_off_full;
    const int pstart = off[c];
    const int pend   = off[GROUPED ? (c + 1) : 1];
    const int m0 = pstart + blockIdx.y * BM;
    if (m0 >= pend) return;
    const int n0 = blockIdx.x * BN;

    const __half* W = Wt + ((size_t)c * NTOT + n0) * K;
    const float* bb = Bbias + (size_t)c * NTOT + n0;

    extern __shared__ __align__(16) char smraw[];
    __shared__ float sBias[BN];

    const int tid  = threadIdx.x;
    const int wid  = tid >> 5;
    const int lane = tid & 31;
    const int wm = (wid >> 2) * 64;
    const int wn = (wid & 3) * 32;

    const uint32_t smBase = smem_u32(smraw);
    if (tid < BN) sBias[tid] = bb[tid];

    float acc[4][4][4];
#pragma unroll
    for (int i = 0; i < 4; i++)
#pragma unroll
        for (int j = 0; j < 4; j++)
#pragma unroll
            for (int k = 0; k < 4; k++) acc[i][j][k] = 0.f;

    auto prefetch = [&](int it) {
        uint32_t aB = smBase + (uint32_t)(it & 1) * STAGE_BYTES;
        uint32_t bB = aB + BM * 128;
        int kt = it * BK;
#pragma unroll
        for (int i = 0; i < 4; i++) {
            int idx = tid + i * NTHR;
            int r = idx >> 3;
            int c16 = idx & 7;
            int p = m0 + r; if (p >= pend) p = pstart;
            const __half* src = A + (size_t)p * K + kt + c16 * 8;
            cp_async16(aB + r * 128 + (uint32_t)((c16 * 16) ^ ((r & 7) << 4)), src);
        }
#pragma unroll
        for (int i = 0; i < 4; i++) {
            int idx = tid + i * NTHR;
            int r = idx >> 3;
            int c16 = idx & 7;
            const __half* src = W + (size_t)r * K + kt + c16 * 8;
            cp_async16(bB + r * 128 + (uint32_t)((c16 * 16) ^ ((r & 7) << 4)), src);
        }
        cp_commit();
    };

    prefetch(0);
    for (int it = 0; it < NIT; ++it) {
        if (it + 1 < NIT) { prefetch(it + 1); cp_wait<1>(); }
        else              { cp_wait<0>(); }
        __syncthreads();
        uint32_t aB = smBase + (uint32_t)(it & 1) * STAGE_BYTES;
        compute_chunk(aB, aB + BM * 128, acc, wm, wn, lane);
        __syncthreads();
    }

    constexpr int CSTR = 136;
    __half* sC = (__half*)smraw;
#pragma unroll
    for (int mi = 0; mi < 4; mi++) {
        int r0 = wm + 16 * mi + (lane >> 2);
#pragma unroll
        for (int ni = 0; ni < 4; ni++) {
            int col = wn + 8 * ni + 2 * (lane & 3);
            float v0 = acc[mi][ni][0] + sBias[col];
            float v1 = acc[mi][ni][1] + sBias[col + 1];
            float v2 = acc[mi][ni][2] + sBias[col];
            float v3 = acc[mi][ni][3] + sBias[col + 1];
            if (ACT == 0) { v0 = sigmoidf_(v0); v1 = sigmoidf_(v1); v2 = sigmoidf_(v2); v3 = sigmoidf_(v3); }
            else          { v0 = tanhf(v0);     v1 = tanhf(v1);     v2 = tanhf(v2);     v3 = tanhf(v3); }
            *(uint32_t*)(sC + r0 * CSTR + col)       = packh2(v0, v1);
            *(uint32_t*)(sC + (r0 + 8) * CSTR + col) = packh2(v2, v3);
        }
    }
    __syncthreads();

#pragma unroll
    for (int i = 0; i < 8; i++) {
        int e = tid + i * NTHR;
        int r = e >> 4, q = e & 15;
        int p = m0 + r;
        if (p < pend) {
            uint4 v = *(const uint4*)(sC + r * CSTR + q * 8);
            *(uint4*)(Out + (size_t)p * out_stride + coloff + n0 + q * 8) = v;
        }
    }
}

// ---------------- MEGA kernel: branch L2 + L3 + heads ----------------
// Block: 128 sorted rows of branch c = blockIdx.z. h1 -> h2 (smem, swizzled) -> h3 (smem) -> 3 dots.
__global__ void __launch_bounds__(NTHR)
mega_kernel(const float* __restrict__ b2v, const float* __restrict__ b3v,
            const float* __restrict__ hWb, const float* __restrict__ hbb,
            const float* __restrict__ hWs, const float* __restrict__ hbs,
            const float* __restrict__ hWt, const float* __restrict__ hbt,
            float* __restrict__ out) {
    const int c = blockIdx.z;
    const int pstart = g_off[c];
    const int pend   = g_off[c + 1];
    const int m0 = pstart + blockIdx.y * BM;
    if (m0 >= pend) return;

    extern __shared__ __align__(16) char smraw[];
    __shared__ int permS[BM];
    __shared__ float sB2[HH], sB3[HH];
    __shared__ float sHW[3][HH];

    const int tid  = threadIdx.x;
    const int wid  = tid >> 5;
    const int lane = tid & 31;
    const int wm = (wid >> 2) * 64;
    const int wn = (wid & 3) * 32;
    const uint32_t smBase = smem_u32(smraw);

    if (tid < BM) {
        int p = m0 + tid;
        permS[tid] = (p < pend) ? g_perm[p] : 0;
    }
    if (tid < HH) {
        sB2[tid] = b2v[c * HH + tid];
        sB3[tid] = b3v[c * HH + tid];
        sHW[0][tid] = hWb[c * HH + tid];
        sHW[1][tid] = hWs[c * HH + tid];
        sHW[2][tid] = hWt[c * HH + tid];
    }

    const __half* h1 = g_h1;
    const __half* W2 = g_W2t + (size_t)c * HH * HH;
    const __half* W3 = g_W3t + (size_t)c * HH * HH;

    float acc[4][4][4];

    // ---------- phase 1: h2 = sigmoid(h1 @ W2^T + b2), into swizzled smem ----------
    auto prefetch1 = [&](int it, int nh) {
        uint32_t aS = smBase + MG_AST0 + (uint32_t)(it & 1) * 16384;
        uint32_t bS = smBase + MG_BST0 + (uint32_t)(it & 1) * 16384;
        int kt = it * BK;
#pragma unroll
        for (int i = 0; i < 4; i++) {
            int idx = tid + i * NTHR;
            int r = idx >> 3;
            int c16 = idx & 7;
            int p = m0 + r; if (p >= pend) p = pstart;
            cp_async16(aS + r * 128 + (uint32_t)((c16 * 16) ^ ((r & 7) << 4)),
                       h1 + (size_t)p * HH + kt + c16 * 8);
        }
#pragma unroll
        for (int i = 0; i < 4; i++) {
            int idx = tid + i * NTHR;
            int r = idx >> 3;
            int c16 = idx & 7;
            cp_async16(bS + r * 128 + (uint32_t)((c16 * 16) ^ ((r & 7) << 4)),
                       W2 + (size_t)(nh * 128 + r) * HH + kt + c16 * 8);
        }
        cp_commit();
    };

    __syncthreads();   // permS / biases ready

    for (int nh = 0; nh < 2; nh++) {
#pragma unroll
        for (int i = 0; i < 4; i++)
#pragma unroll
            for (int j = 0; j < 4; j++)
#pragma unroll
                for (int k = 0; k < 4; k++) acc[i][j][k] = 0.f;
        prefetch1(0, nh);
        for (int it = 0; it < 4; ++it) {
            if (it + 1 < 4) { prefetch1(it + 1, nh); cp_wait<1>(); }
            else            { cp_wait<0>(); }
            __syncthreads();
            compute_chunk(smBase + MG_AST0 + (uint32_t)(it & 1) * 16384,
                          smBase + MG_BST0 + (uint32_t)(it & 1) * 16384,
                          acc, wm, wn, lane);
            __syncthreads();
        }
        // epilogue -> h2 (chunked swizzled layout for phase-2 ldmatrix)
#pragma unroll
        for (int mi = 0; mi < 4; mi++) {
            int r0 = wm + 16 * mi + (lane >> 2);
#pragma unroll
            for (int ni = 0; ni < 4; ni++) {
                int n = nh * 128 + wn + 8 * ni + 2 * (lane & 3);
                float v0 = sigmoidf_(acc[mi][ni][0] + sB2[n]);
                float v1 = sigmoidf_(acc[mi][ni][1] + sB2[n + 1]);
                float v2 = sigmoidf_(acc[mi][ni][2] + sB2[n]);
                float v3 = sigmoidf_(acc[mi][ni][3] + sB2[n + 1]);
                int chunk = n >> 6;
                int cw = (((n & 63) >> 3) << 4);
                int bo = (n & 7) * 2;
                *(uint32_t*)(smraw + MG_H2 + chunk * 16384 + r0 * 128 +
                             (cw ^ ((r0 & 7) << 4)) + bo) = packh2(v0, v1);
                int r1 = r0 + 8;
                *(uint32_t*)(smraw + MG_H2 + chunk * 16384 + r1 * 128 +
                             (cw ^ ((r1 & 7) << 4)) + bo) = packh2(v2, v3);
            }
        }
    }
    __syncthreads();   // h2 complete

    // ---------- phase 2: h3 = sigmoid(h2 @ W3^T + b3), halves into AST / BST regions ----------
    auto prefetch2 = [&](int it, int nh) {
        uint32_t bS = smBase + MG_BST0 + (uint32_t)(it & 1) * 16384;
        int kt = it * BK;
#pragma unroll
        for (int i = 0; i < 4; i++) {
            int idx = tid + i * NTHR;
            int r = idx >> 3;
            int c16 = idx & 7;
            cp_async16(bS + r * 128 + (uint32_t)((c16 * 16) ^ ((r & 7) << 4)),
                       W3 + (size_t)(nh * 128 + r) * HH + kt + c16 * 8);
        }
        cp_commit();
    };

    // nh=0 uses B stages; h3 lo half lands in AST region afterwards.
    // nh=1 h3 hi half lands in BST region after its last compute.
    for (int nh = 0; nh < 2; nh++) {
#pragma unroll
        for (int i = 0; i < 4; i++)
#pragma unroll
            for (int j = 0; j < 4; j++)
#pragma unroll
                for (int k = 0; k < 4; k++) acc[i][j][k] = 0.f;
        prefetch2(0, nh);
        for (int it = 0; it < 4; ++it) {
            if (it + 1 < 4) { prefetch2(it + 1, nh); cp_wait<1>(); }
            else            { cp_wait<0>(); }
            __syncthreads();
            compute_chunk(smBase + MG_H2 + (uint32_t)it * 16384,
                          smBase + MG_BST0 + (uint32_t)(it & 1) * 16384,
                          acc, wm, wn, lane);
            __syncthreads();
        }
        // epilogue -> h3 half (plain [128][128] fp16, 256B rows)
        char* dst = smraw + (nh == 0 ? MG_AST0 : MG_BST0);
#pragma unroll
        for (int mi = 0; mi < 4; mi++) {
            int r0 = wm + 16 * mi + (lane >> 2);
#pragma unroll
            for (int ni = 0; ni < 4; ni++) {
                int cl = wn + 8 * ni + 2 * (lane & 3);
                int n = nh * 128 + cl;
                float v0 = sigmoidf_(acc[mi][ni][0] + sB3[n]);
                float v1 = sigmoidf_(acc[mi][ni][1] + sB3[n + 1]);
                float v2 = sigmoidf_(acc[mi][ni][2] + sB3[n]);
                float v3 = sigmoidf_(acc[mi][ni][3] + sB3[n + 1]);
                *(uint32_t*)(dst + r0 * 256 + cl * 2)       = packh2(v0, v1);
                *(uint32_t*)(dst + (r0 + 8) * 256 + cl * 2) = packh2(v2, v3);
            }
        }
        __syncthreads();
    }

    // ---------- phase 3: heads ----------
    const __half* lo = (const __half*)(smraw + MG_AST0);
    const __half* hi = (const __half*)(smraw + MG_BST0);
    float hb = hbb[c], hs = hbs[c], ht = hbt[c];
#pragma unroll
    for (int rr = 0; rr < 16; rr++) {
        int r = wid * 16 + rr;
        int p = m0 + r;
        float sb = 0.f, ss = 0.f, st = 0.f;
        int col0 = lane * 8;
        const __half* src = (col0 < 128) ? (lo + r * 128 + col0) : (hi + r * 128 + col0 - 128);
#pragma unroll
        for (int j = 0; j < 8; j++) {
            float hv = __half2float(src[j]);
            int col = col0 + j;
            sb = fmaf(hv, sHW[0][col], sb);
            ss = fmaf(hv, sHW[1][col], ss);
            st = fmaf(hv, sHW[2][col], st);
        }
#pragma unroll
        for (int o = 16; o; o >>= 1) {
            sb += __shfl_xor_sync(0xFFFFFFFFu, sb, o);
            ss += __shfl_xor_sync(0xFFFFFFFFu, ss, o);
            st += __shfl_xor_sync(0xFFFFFFFFu, st, o);
        }
        if (lane == 0 && p < pend) {
            int ro = permS[r];
            out[ro]          = sigmoidf_(sb + hb);
            out[BB + ro]     = tanhf(ss + hs);
            out[2 * BB + ro] = sigmoidf_(st + ht);
        }
    }
}

// ---------------- launcher ----------------
extern "C" void kernel_launch(void* const* d_in, const int* in_sizes, int n_in,
                              void* d_out, int out_size) {
    const float* rgb  = (const float*)d_in[0];
    const float* spd  = (const float*)d_in[1];
    const int*   cmd  = (const int*)  d_in[2];
    const float* sW1  = (const float*)d_in[3];
    const float* sb1  = (const float*)d_in[4];
    const float* sW2  = (const float*)d_in[5];
    const float* sb2  = (const float*)d_in[6];
    const float* sW3  = (const float*)d_in[7];
    const float* sb3  = (const float*)d_in[8];
    const float* W1   = (const float*)d_in[9];
    const float* b1   = (const float*)d_in[10];
    const float* W2   = (const float*)d_in[11];
    const float* b2   = (const float*)d_in[12];
    const float* W3   = (const float*)d_in[13];
    const float* b3   = (const float*)d_in[14];
    const float* hWb  = (const float*)d_in[15];
    const float* hbb  = (const float*)d_in[16];
    const float* hWs  = (const float*)d_in[17];
    const float* hbs  = (const float*)d_in[18];
    const float* hWt  = (const float*)d_in[19];
    const float* hbt  = (const float*)d_in[20];
    float* out = (float*)d_out;

    void* p;
    cudaGetSymbolAddress(&p, g_s1);   __half* s1  = (__half*)p;
    cudaGetSymbolAddress(&p, g_s2);   __half* s2  = (__half*)p;
    cudaGetSymbolAddress(&p, g_xbf);  __half* xbf = (__half*)p;
    cudaGetSymbolAddress(&p, g_h1);   __half* h1  = (__half*)p;
    cudaGetSymbolAddress(&p, g_W1t);  __half* W1t = (__half*)p;
    cudaGetSymbolAddress(&p, g_W2t);  __half* W2t = (__half*)p;
    cudaGetSymbolAddress(&p, g_W3t);  __half* W3t = (__half*)p;
    cudaGetSymbolAddress(&p, g_sW2t); __half* sW2t = (__half*)p;
    cudaGetSymbolAddress(&p, g_sW3t); __half* sW3t = (__half*)p;

    cudaFuncSetAttribute(mma_gemm_kernel<DSPD, DSPD, 1, false>,
                         cudaFuncAttributeMaxDynamicSharedMemorySize, SMEM_BYTES);
    cudaFuncSetAttribute(mma_gemm_kernel<DIN, HH, 0, true>,
                         cudaFuncAttributeMaxDynamicSharedMemorySize, SMEM_BYTES);
    cudaFuncSetAttribute(mega_kernel,
                         cudaFuncAttributeMaxDynamicSharedMemorySize, MG_SMEM);

    // bucket rows by cmd
    zero_kernel<<<1, 32>>>();
    hist_kernel<<<BB / 256, 256>>>(cmd);
    scan_kernel<<<1, 1>>>();
    scatter_kernel<<<BB / 256, 256>>>(cmd);

    // weights -> fp16 [N,K]
    {
        dim3 b(32, 8);
        transpose_h2_kernel<<<dim3(HH / 32, DIN / 32, CC), b>>>(W1, W1t, W1, W1t, DIN, HH, CC);
        transpose_h2_kernel<<<dim3(HH / 32, HH / 32, 2 * CC), b>>>(W2, W2t, W3, W3t, HH, HH, CC);
        transpose_h2_kernel<<<dim3(DSPD / 32, DSPD / 32, 2), b>>>(sW2, sW2t, sW3, sW3t, DSPD, DSPD, 1);
    }

    // sorted-space inputs
    gather_rgb_kernel<<<(BB * 64) / 256, 256>>>(rgb);
    spd_l1_kernel<<<(BB * 16) / 256, 256>>>(spd, sW1, sb1);

    // speed MLP layers 2,3 (layer 3 writes concat columns of xbf)
    {
        dim3 g(1, BB / BM, 1);
        mma_gemm_kernel<DSPD, DSPD, 1, false><<<g, NTHR, SMEM_BYTES>>>(s1, sW2t, sb2, s2, DSPD, 0);
        mma_gemm_kernel<DSPD, DSPD, 1, false><<<g, NTHR, SMEM_BYTES>>>(s2, sW3t, sb3, xbf, DIN, DRGB);
    }

    // branch L1: x -> h1
    {
        dim3 g1(HH / BN, BB / BM, CC);
        mma_gemm_kernel<DIN, HH, 0, true><<<g1, NTHR, SMEM_BYTES>>>(xbf, W1t, b1, h1, HH, 0);
    }

    // branch L2 + L3 + heads fused
    {
        dim3 g2(1, BB / BM, CC);
        mega_kernel<<<g2, NTHR, MG_SMEM>>>(b2, b3, hWb, hbb, hWs, hbs, hWt, hbt, out);
    }
}

// round 11
// speedup vs baseline: 1.1898x; 1.1898x over previous
#include <cuda_runtime.h>
#include <cuda_fp16.h>
#include <cstdint>
#include <math.h>

#define BB   32768
#define DRGB 512
#define DSPD 128
#define DIN  640
#define HH   256
#define CC   7

#define BM   128
#define BN   128
#define BK   64
#define NTHR 256
#define STAGE_BYTES 32768        // (128 + 128) rows * 128B
#define SMEM_BYTES  (2 * STAGE_BYTES)

// ---------------- device scratch ----------------
__device__ int g_hpart[128][8];
__device__ int g_off[8];
__device__ int g_pos[8];
__device__ int g_perm[BB];
__device__ int g_off_full[2] = {0, BB};

__device__ __half g_s1[BB * DSPD];
__device__ __half g_s2[BB * DSPD];
__device__ __half g_xbf[(size_t)BB * DIN];     // sorted concat [rgb | sfeat]
__device__ __half g_h1[(size_t)BB * HH];
__device__ __half g_h2[(size_t)BB * HH];
__device__ __half g_h3[(size_t)BB * HH];

// fp16 transposed weights: [C][N][K]
__device__ __half g_W1t[(size_t)CC * HH * DIN];
__device__ __half g_W2t[(size_t)CC * HH * HH];
__device__ __half g_W3t[(size_t)CC * HH * HH];
__device__ __half g_sW2t[DSPD * DSPD];
__device__ __half g_sW3t[DSPD * DSPD];

__device__ __forceinline__ float sigmoidf_(float x) { return 1.0f / (1.0f + expf(-x)); }

// ---------------- PTX helpers ----------------
__device__ __forceinline__ uint32_t smem_u32(const void* p) {
    return (uint32_t)__cvta_generic_to_shared(p);
}
__device__ __forceinline__ void cp_async16(uint32_t dst, const void* src) {
    asm volatile("cp.async.cg.shared.global [%0], [%1], 16;\n" :: "r"(dst), "l"(src) : "memory");
}
__device__ __forceinline__ void cp_commit() { asm volatile("cp.async.commit_group;\n" ::: "memory"); }
template <int N> __device__ __forceinline__ void cp_wait() {
    asm volatile("cp.async.wait_group %0;\n" :: "n"(N) : "memory");
}
__device__ __forceinline__ void ldmx4(uint32_t& r0, uint32_t& r1, uint32_t& r2, uint32_t& r3,
                                      uint32_t addr) {
    asm volatile("ldmatrix.sync.aligned.m8n8.x4.shared.b16 {%0,%1,%2,%3}, [%4];"
                 : "=r"(r0), "=r"(r1), "=r"(r2), "=r"(r3) : "r"(addr));
}
__device__ __forceinline__ void mma16816(float* d, const uint32_t* a, const uint32_t* b) {
    asm volatile(
        "mma.sync.aligned.m16n8k16.row.col.f32.f16.f16.f32 "
        "{%0,%1,%2,%3}, {%4,%5,%6,%7}, {%8,%9}, {%0,%1,%2,%3};"
        : "+f"(d[0]), "+f"(d[1]), "+f"(d[2]), "+f"(d[3])
        : "r"(a[0]), "r"(a[1]), "r"(a[2]), "r"(a[3]), "r"(b[0]), "r"(b[1]));
}
__device__ __forceinline__ uint32_t packh2(float a, float b) {
    __half2 h = __floats2half2_rn(a, b);
    return *(uint32_t*)&h;
}

// ---------------- bucketing ----------------
__global__ void hist_kernel(const int* __restrict__ cmd) {
    __shared__ int sc[8];
    if (threadIdx.x < 8) sc[threadIdx.x] = 0;
    __syncthreads();
    int i = blockIdx.x * blockDim.x + threadIdx.x;
    if (i < BB) atomicAdd(&sc[cmd[i]], 1);
    __syncthreads();
    if (threadIdx.x < 8) g_hpart[blockIdx.x][threadIdx.x] = sc[threadIdx.x];
}

__global__ void scan_kernel() {
    __shared__ int cnt[8];
    int w = threadIdx.x >> 5, lane = threadIdx.x & 31;
    int s = 0;
    for (int k = lane; k < 128; k += 32) s += g_hpart[k][w];
#pragma unroll
    for (int o = 16; o; o >>= 1) s += __shfl_xor_sync(0xFFFFFFFFu, s, o);
    if (lane == 0) cnt[w] = s;
    __syncthreads();
    if (threadIdx.x == 0) {
        g_off[0] = 0;
        for (int c = 0; c < CC; c++) { g_off[c + 1] = g_off[c] + cnt[c]; g_pos[c] = g_off[c]; }
    }
}

__global__ void scatter_kernel(const int* __restrict__ cmd) {
    int i = blockIdx.x * blockDim.x + threadIdx.x;
    if (i >= BB) return;
    int c = cmd[i];
    int lane = threadIdx.x & 31;
    unsigned mask = __match_any_sync(0xFFFFFFFFu, c);
    int leader = __ffs(mask) - 1;
    int rank = __popc(mask & ((1u << lane) - 1));
    int base = 0;
    if (lane == leader) base = atomicAdd(&g_pos[c], __popc(mask));
    base = __shfl_sync(0xFFFFFFFFu, base, leader);
    g_perm[base + rank] = i;
}

// ---------------- weight transpose + fp32->fp16 (two tensors batched via z) ----------------
__global__ void transpose_h2_kernel(const float* __restrict__ srcA, __half* __restrict__ dstA,
                                    const float* __restrict__ srcB, __half* __restrict__ dstB,
                                    int R, int C_, int zsplit) {
    __shared__ float t[32][33];
    int z = blockIdx.z;
    const float* src = (z < zsplit) ? srcA : srcB;
    __half* dst = (z < zsplit) ? dstA : dstB;
    int zz = (z < zsplit) ? z : z - zsplit;
    src += (size_t)zz * R * C_;
    dst += (size_t)zz * R * C_;
    int c0 = blockIdx.x * 32, r0 = blockIdx.y * 32;
    int tx = threadIdx.x, ty = threadIdx.y;
#pragma unroll
    for (int k = 0; k < 4; k++)
        t[ty + 8 * k][tx] = src[(size_t)(r0 + ty + 8 * k) * C_ + c0 + tx];
    __syncthreads();
#pragma unroll
    for (int k = 0; k < 4; k++)
        dst[(size_t)(c0 + ty + 8 * k) * R + r0 + tx] = __float2half_rn(t[tx][ty + 8 * k]);
}

// ---------------- speed-MLP layer 1 (rank-1), sorted output, fp16 ----------------
__global__ void spd_l1_kernel(const float* __restrict__ spd,
                              const float* __restrict__ W1,
                              const float* __restrict__ b1) {
    int idx = blockIdx.x * blockDim.x + threadIdx.x;
    if (idx >= BB * 16) return;
    int p = idx >> 4;
    int j8 = (idx & 15) * 8;
    float s = spd[g_perm[p]];
    uint4 o;
    float4 w0 = *(const float4*)(W1 + j8), w1 = *(const float4*)(W1 + j8 + 4);
    float4 c0 = *(const float4*)(b1 + j8), c1 = *(const float4*)(b1 + j8 + 4);
    o.x = packh2(tanhf(fmaf(s, w0.x, c0.x)), tanhf(fmaf(s, w0.y, c0.y)));
    o.y = packh2(tanhf(fmaf(s, w0.z, c0.z)), tanhf(fmaf(s, w0.w, c0.w)));
    o.z = packh2(tanhf(fmaf(s, w1.x, c1.x)), tanhf(fmaf(s, w1.y, c1.y)));
    o.w = packh2(tanhf(fmaf(s, w1.z, c1.z)), tanhf(fmaf(s, w1.w, c1.w)));
    *(uint4*)(g_s1 + (size_t)p * DSPD + j8) = o;
}

// ---------------- rgb gather + fp32->fp16 ----------------
__global__ void gather_rgb_kernel(const float* __restrict__ rgb) {
    int idx = blockIdx.x * blockDim.x + threadIdx.x;
    if (idx >= BB * 64) return;
    int p = idx >> 6;
    int j8 = (idx & 63) * 8;
    int row = g_perm[p];
    float4 v0 = *(const float4*)(rgb + (size_t)row * DRGB + j8);
    float4 v1 = *(const float4*)(rgb + (size_t)row * DRGB + j8 + 4);
    uint4 o;
    o.x = packh2(v0.x, v0.y);
    o.y = packh2(v0.z, v0.w);
    o.z = packh2(v1.x, v1.y);
    o.w = packh2(v1.z, v1.w);
    *(uint4*)(g_xbf + (size_t)p * DIN + j8) = o;
}

// ---------------- fp16 mma.sync GEMM ----------------
template <int K, int NTOT, int ACT, bool GROUPED>
__global__ void __launch_bounds__(NTHR)
mma_gemm_kernel(const __half* __restrict__ A,
                const __half* __restrict__ Wt,
                const float* __restrict__ Bbias,
                __half* __restrict__ Out, int out_stride, int coloff) {
    constexpr int NIT = K / BK;
    const int c = GROUPED ? blockIdx.z : 0;
    const int* off = GROUPED ? g_off : g_off_full;
    const int pstart = off[c];
    const int pend   = off[GROUPED ? (c + 1) : 1];
    const int m0 = pstart + blockIdx.y * BM;
    if (m0 >= pend) return;
    const int n0 = blockIdx.x * BN;

    const __half* W = Wt + ((size_t)c * NTOT + n0) * K;
    const float* bb = Bbias + (size_t)c * NTOT + n0;

    extern __shared__ __align__(16) char smraw[];
    __shared__ float sBias[BN];

    const int tid  = threadIdx.x;
    const int wid  = tid >> 5;
    const int lane = tid & 31;
    const int wm = (wid >> 2) * 64;
    const int wn = (wid & 3) * 32;

    const uint32_t smBase = smem_u32(smraw);
    if (tid < BN) sBias[tid] = bb[tid];

    float acc[4][4][4];
#pragma unroll
    for (int i = 0; i < 4; i++)
#pragma unroll
        for (int j = 0; j < 4; j++)
#pragma unroll
            for (int k = 0; k < 4; k++) acc[i][j][k] = 0.f;

    auto prefetch = [&](int it) {
        uint32_t aB = smBase + (uint32_t)(it & 1) * STAGE_BYTES;
        uint32_t bB = aB + BM * 128;
        int kt = it * BK;
#pragma unroll
        for (int i = 0; i < 4; i++) {
            int idx = tid + i * NTHR;
            int r = idx >> 3;
            int c16 = idx & 7;
            int p = m0 + r; if (p >= pend) p = pstart;
            const __half* src = A + (size_t)p * K + kt + c16 * 8;
            cp_async16(aB + r * 128 + (uint32_t)((c16 * 16) ^ ((r & 7) << 4)), src);
        }
#pragma unroll
        for (int i = 0; i < 4; i++) {
            int idx = tid + i * NTHR;
            int r = idx >> 3;
            int c16 = idx & 7;
            const __half* src = W + (size_t)r * K + kt + c16 * 8;
            cp_async16(bB + r * 128 + (uint32_t)((c16 * 16) ^ ((r & 7) << 4)), src);
        }
        cp_commit();
    };

    prefetch(0);

    for (int it = 0; it < NIT; ++it) {
        if (it + 1 < NIT) { prefetch(it + 1); cp_wait<1>(); }
        else              { cp_wait<0>(); }
        __syncthreads();

        uint32_t aB = smBase + (uint32_t)(it & 1) * STAGE_BYTES;
        uint32_t bB = aB + BM * 128;

#pragma unroll
        for (int ks = 0; ks < BK / 16; ks++) {
            uint32_t a[4][4], b[4][2];
            int cbA = ks * 32 + ((lane >> 4) << 4);
#pragma unroll
            for (int mi = 0; mi < 4; mi++) {
                int r = wm + 16 * mi + (lane & 15);
                ldmx4(a[mi][0], a[mi][1], a[mi][2], a[mi][3],
                      aB + r * 128 + (uint32_t)(cbA ^ ((r & 7) << 4)));
            }
            int cbB = ks * 32 + ((lane & 8) << 1);
#pragma unroll
            for (int nj = 0; nj < 2; nj++) {
                int r = wn + 16 * nj + (lane & 7) + ((lane & 16) >> 1);
                uint32_t t0, t1, t2, t3;
                ldmx4(t0, t1, t2, t3, bB + r * 128 + (uint32_t)(cbB ^ ((r & 7) << 4)));
                b[2 * nj][0] = t0; b[2 * nj][1] = t1;
                b[2 * nj + 1][0] = t2; b[2 * nj + 1][1] = t3;
            }
#pragma unroll
            for (int mi = 0; mi < 4; mi++)
#pragma unroll
                for (int ni = 0; ni < 4; ni++)
                    mma16816(acc[mi][ni], a[mi], b[ni]);
        }
        __syncthreads();
    }

    constexpr int CSTR = 136;
    __half* sC = (__half*)smraw;
#pragma unroll
    for (int mi = 0; mi < 4; mi++) {
        int r0 = wm + 16 * mi + (lane >> 2);
#pragma unroll
        for (int ni = 0; ni < 4; ni++) {
            int col = wn + 8 * ni + 2 * (lane & 3);
            float v0 = acc[mi][ni][0] + sBias[col];
            float v1 = acc[mi][ni][1] + sBias[col + 1];
            float v2 = acc[mi][ni][2] + sBias[col];
            float v3 = acc[mi][ni][3] + sBias[col + 1];
            if (ACT == 0) { v0 = sigmoidf_(v0); v1 = sigmoidf_(v1); v2 = sigmoidf_(v2); v3 = sigmoidf_(v3); }
            else          { v0 = tanhf(v0);     v1 = tanhf(v1);     v2 = tanhf(v2);     v3 = tanhf(v3); }
            *(uint32_t*)(sC + r0 * CSTR + col)       = packh2(v0, v1);
            *(uint32_t*)(sC + (r0 + 8) * CSTR + col) = packh2(v2, v3);
        }
    }
    __syncthreads();

#pragma unroll
    for (int i = 0; i < 8; i++) {
        int e = tid + i * NTHR;
        int r = e >> 4, q = e & 15;
        int p = m0 + r;
        if (p < pend) {
            uint4 v = *(const uint4*)(sC + r * CSTR + q * 8);
            *(uint4*)(Out + (size_t)p * out_stride + coloff + n0 + q * 8) = v;
        }
    }
}

// ---------------- heads ----------------
__global__ void heads_kernel(const int* __restrict__ cmd,
                             const float* __restrict__ hWb, const float* __restrict__ hbb,
                             const float* __restrict__ hWs, const float* __restrict__ hbs,
                             const float* __restrict__ hWt, const float* __restrict__ hbt,
                             float* __restrict__ out) {
    int p = blockIdx.x * 8 + (threadIdx.x >> 5);
    int lane = threadIdx.x & 31;
    if (p >= BB) return;
    int r = g_perm[p];
    int c = cmd[r];
    const __half* h = g_h3 + (size_t)p * HH;
    float sb = 0.f, ss = 0.f, st = 0.f;
#pragma unroll
    for (int i = 0; i < 8; i++) {
        int k = lane + 32 * i;
        float hv = __half2float(h[k]);
        sb = fmaf(hv, hWb[c * HH + k], sb);
        ss = fmaf(hv, hWs[c * HH + k], ss);
        st = fmaf(hv, hWt[c * HH + k], st);
    }
#pragma unroll
    for (int o = 16; o; o >>= 1) {
        sb += __shfl_xor_sync(0xFFFFFFFFu, sb, o);
        ss += __shfl_xor_sync(0xFFFFFFFFu, ss, o);
        st += __shfl_xor_sync(0xFFFFFFFFu, st, o);
    }
    if (lane == 0) {
        out[r]          = sigmoidf_(sb + hbb[c]);
        out[BB + r]     = tanhf(ss + hbs[c]);
        out[2 * BB + r] = sigmoidf_(st + hbt[c]);
    }
}

// ---------------- launcher ----------------
extern "C" void kernel_launch(void* const* d_in, const int* in_sizes, int n_in,
                              void* d_out, int out_size) {
    const float* rgb  = (const float*)d_in[0];
    const float* spd  = (const float*)d_in[1];
    const int*   cmd  = (const int*)  d_in[2];
    const float* sW1  = (const float*)d_in[3];
    const float* sb1  = (const float*)d_in[4];
    const float* sW2  = (const float*)d_in[5];
    const float* sb2  = (const float*)d_in[6];
    const float* sW3  = (const float*)d_in[7];
    const float* sb3  = (const float*)d_in[8];
    const float* W1   = (const float*)d_in[9];
    const float* b1   = (const float*)d_in[10];
    const float* W2   = (const float*)d_in[11];
    const float* b2   = (const float*)d_in[12];
    const float* W3   = (const float*)d_in[13];
    const float* b3   = (const float*)d_in[14];
    const float* hWb  = (const float*)d_in[15];
    const float* hbb  = (const float*)d_in[16];
    const float* hWs  = (const float*)d_in[17];
    const float* hbs  = (const float*)d_in[18];
    const float* hWt  = (const float*)d_in[19];
    const float* hbt  = (const float*)d_in[20];
    float* out = (float*)d_out;

    void* p;
    cudaGetSymbolAddress(&p, g_s1);   __half* s1  = (__half*)p;
    cudaGetSymbolAddress(&p, g_s2);   __half* s2  = (__half*)p;
    cudaGetSymbolAddress(&p, g_xbf);  __half* xbf = (__half*)p;
    cudaGetSymbolAddress(&p, g_h1);   __half* h1  = (__half*)p;
    cudaGetSymbolAddress(&p, g_h2);   __half* h2  = (__half*)p;
    cudaGetSymbolAddress(&p, g_h3);   __half* h3  = (__half*)p;
    cudaGetSymbolAddress(&p, g_W1t);  __half* W1t = (__half*)p;
    cudaGetSymbolAddress(&p, g_W2t);  __half* W2t = (__half*)p;
    cudaGetSymbolAddress(&p, g_W3t);  __half* W3t = (__half*)p;
    cudaGetSymbolAddress(&p, g_sW2t); __half* sW2t = (__half*)p;
    cudaGetSymbolAddress(&p, g_sW3t); __half* sW3t = (__half*)p;

    cudaFuncSetAttribute(mma_gemm_kernel<DSPD, DSPD, 1, false>,
                         cudaFuncAttributeMaxDynamicSharedMemorySize, SMEM_BYTES);
    cudaFuncSetAttribute(mma_gemm_kernel<DIN, HH, 0, true>,
                         cudaFuncAttributeMaxDynamicSharedMemorySize, SMEM_BYTES);
    cudaFuncSetAttribute(mma_gemm_kernel<HH, HH, 0, true>,
                         cudaFuncAttributeMaxDynamicSharedMemorySize, SMEM_BYTES);

    // lazy-created side streams + fork/join events (infra only; identical work every call)
    static cudaStream_t sT = nullptr, sS = nullptr;
    static cudaEvent_t evRoot = nullptr, evT = nullptr, evScat = nullptr, evSpd = nullptr;
    if (sT == nullptr) {
        cudaStreamCreateWithFlags(&sT, cudaStreamNonBlocking);
        cudaStreamCreateWithFlags(&sS, cudaStreamNonBlocking);
        cudaEventCreateWithFlags(&evRoot, cudaEventDisableTiming);
        cudaEventCreateWithFlags(&evT,    cudaEventDisableTiming);
        cudaEventCreateWithFlags(&evScat, cudaEventDisableTiming);
        cudaEventCreateWithFlags(&evSpd,  cudaEventDisableTiming);
    }

    // fork: transposes on sT, concurrent with bucketing on default stream
    cudaEventRecord(evRoot, 0);
    cudaStreamWaitEvent(sT, evRoot, 0);
    {
        dim3 b(32, 8);
        transpose_h2_kernel<<<dim3(HH / 32, DIN / 32, CC), b, 0, sT>>>(W1, W1t, W1, W1t, DIN, HH, CC);
        transpose_h2_kernel<<<dim3(HH / 32, HH / 32, 2 * CC), b, 0, sT>>>(W2, W2t, W3, W3t, HH, HH, CC);
        transpose_h2_kernel<<<dim3(DSPD / 32, DSPD / 32, 2), b, 0, sT>>>(sW2, sW2t, sW3, sW3t, DSPD, DSPD, 1);
        cudaEventRecord(evT, sT);
    }

    // default stream: bucketing
    hist_kernel<<<BB / 256, 256>>>(cmd);
    scan_kernel<<<1, 256>>>();
    scatter_kernel<<<BB / 256, 256>>>(cmd);
    cudaEventRecord(evScat, 0);

    // sS: speed branch (perm -> s1 -> s2 -> xbf[:,512:640]), overlaps with rgb gather
    cudaStreamWaitEvent(sS, evScat, 0);
    spd_l1_kernel<<<(BB * 16) / 256, 256, 0, sS>>>(spd, sW1, sb1);
    cudaStreamWaitEvent(sS, evT, 0);
    {
        dim3 g(1, BB / BM, 1);
        mma_gemm_kernel<DSPD, DSPD, 1, false><<<g, NTHR, SMEM_BYTES, sS>>>(s1, sW2t, sb2, s2, DSPD, 0);
        mma_gemm_kernel<DSPD, DSPD, 1, false><<<g, NTHR, SMEM_BYTES, sS>>>(s2, sW3t, sb3, xbf, DIN, DRGB);
    }
    cudaEventRecord(evSpd, sS);

    // default stream: rgb gather (xbf[:,0:512])
    gather_rgb_kernel<<<(BB * 64) / 256, 256>>>(rgb);

    // join: L1 needs xbf complete + W1t
    cudaStreamWaitEvent(0, evT, 0);
    cudaStreamWaitEvent(0, evSpd, 0);

    // branch MLPs
    {
        dim3 g1(HH / BN, BB / BM, CC);
        mma_gemm_kernel<DIN, HH, 0, true><<<g1, NTHR, SMEM_BYTES>>>(xbf, W1t, b1, h1, HH, 0);
        mma_gemm_kernel<HH,  HH, 0, true><<<g1, NTHR, SMEM_BYTES>>>(h1,  W2t, b2, h2, HH, 0);
        mma_gemm_kernel<HH,  HH, 0, true><<<g1, NTHR, SMEM_BYTES>>>(h2,  W3t, b3, h3, HH, 0);
    }

    // heads
    heads_kernel<<<BB / 8, 256>>>(cmd, hWb, hbb, hWs, hbs, hWt, hbt, out);
}